// round 4
// baseline (speedup 1.0000x reference)
#include <cuda_runtime.h>
#include <cstdint>
#include <cstddef>

#define NB     64
#define LT     512
#define DIN    1024
#define HID    2048
#define NCTA   128
#define UPC    16          // hidden units per CTA
#define TPB    128         // 4 warps
#define KC     64
#define NCHUNK (HID / KC)  // 32
#define TSTR   68          // padded smem row stride (floats)
#define TILEF  (64 * TSTR)
#define SMEM_FLOATS (7 * TILEF + 1024 + 128)
#define SMEM_BYTES  (SMEM_FLOATS * 4)

// ---------------- device globals (scratch) ----------------
__device__ __align__(16) float    g_Wt[4u * HID * HID];  // tf32-rounded weights
__device__ __align__(16) float    g_S[LT * NB];          // invariant sums S[t][n]
__device__ __align__(16) float    g_h[2][HID * NB];      // h double buffer, [k][n]
__device__ unsigned g_bar_count = 0;
__device__ unsigned g_bar_gen   = 0;

// ---------------- helpers ----------------
__device__ __forceinline__ float tf32_rna(float x) {
    unsigned u;
    asm("cvt.rna.tf32.f32 %0, %1;" : "=r"(u) : "f"(x));
    return __uint_as_float(u);
}

__device__ __forceinline__ void cp_async16(void* dst_smem, const void* src_gmem) {
    unsigned d = (unsigned)__cvta_generic_to_shared(dst_smem);
    asm volatile("cp.async.cg.shared.global [%0], [%1], 16;\n" :: "r"(d), "l"(src_gmem));
}

__device__ __forceinline__ void mma_tf32(float* c, const unsigned* a, const unsigned* b) {
    asm volatile(
        "mma.sync.aligned.m16n8k8.row.col.f32.tf32.tf32.f32 "
        "{%0,%1,%2,%3}, {%4,%5,%6,%7}, {%8,%9}, {%0,%1,%2,%3};\n"
        : "+f"(c[0]), "+f"(c[1]), "+f"(c[2]), "+f"(c[3])
        : "r"(a[0]), "r"(a[1]), "r"(a[2]), "r"(a[3]), "r"(b[0]), "r"(b[1]));
}

__device__ __forceinline__ float sigmoid_f(float x) { return 1.0f / (1.0f + __expf(-x)); }
__device__ __forceinline__ float tanh_f(float x)    { return 1.0f - 2.0f / (__expf(2.0f * x) + 1.0f); }

__device__ __forceinline__ void grid_bar() {
    __threadfence();
    __syncthreads();
    if (threadIdx.x == 0) {
        unsigned gen = *(volatile unsigned*)&g_bar_gen;
        __threadfence();
        if (atomicAdd(&g_bar_count, 1u) == NCTA - 1u) {
            g_bar_count = 0u;
            __threadfence();
            atomicAdd(&g_bar_gen, 1u);
        } else {
            while (*(volatile unsigned*)&g_bar_gen == gen) { __nanosleep(32); }
        }
    }
    __syncthreads();
}

// ---------------- prep kernels ----------------
__global__ void k_prep_w(const float* __restrict__ W) {
    size_t i = (size_t)blockIdx.x * 256 + threadIdx.x;   // 4,194,304 float4s
    float4 v = ((const float4*)W)[i];
    v.x = tf32_rna(v.x); v.y = tf32_rna(v.y);
    v.z = tf32_rna(v.z); v.w = tf32_rna(v.w);
    ((float4*)g_Wt)[i] = v;
}

__global__ void k_prep_s(const float* __restrict__ X) {
    __shared__ float red[4];
    int n = blockIdx.x >> 9;
    int t = blockIdx.x & 511;
    const float* p = X + ((size_t)n * LT + t) * DIN;
    float s = 0.0f;
    for (int d = threadIdx.x; d < DIN; d += 128) s += p[d];
    #pragma unroll
    for (int o = 16; o > 0; o >>= 1) s += __shfl_down_sync(0xffffffffu, s, o);
    if ((threadIdx.x & 31) == 0) red[threadIdx.x >> 5] = s;
    __syncthreads();
    if (threadIdx.x == 0) g_S[t * NB + n] = red[0] + red[1] + red[2] + red[3];
}

__global__ void k_prep_h0(const float* __restrict__ H0) {
    int i = blockIdx.x * 256 + threadIdx.x;  // 131072 elements; H0 is [n][k]
    int n = i >> 11;
    int k = i & 2047;
    g_h[1][k * NB + n] = tf32_rna(H0[i]);    // step 0 reads buffer 1
}

// ---------------- chunk loader ----------------
__device__ __forceinline__ void load_chunk(int lck, int tid, int cta,
                                           const float* __restrict__ hr,
                                           float* shA, float* shB) {
    int buf = lck % 3;
    int k0  = lck * KC;
    float* A = shA + buf * TILEF;
    float* B = shB + buf * TILEF;
    #pragma unroll
    for (int i = tid; i < 1024; i += TPB) {     // 64 rows x 16 float4
        int r  = i >> 4;
        int c4 = (i & 15) << 2;
        const float* src =
            g_Wt + ((size_t)((r >> 4) * HID + cta * UPC + (r & 15))) * HID + k0 + c4;
        cp_async16(A + r * TSTR + c4, src);
    }
    #pragma unroll
    for (int i = tid; i < 1024; i += TPB) {     // 64 k-rows x 16 float4
        int kk = i >> 4;
        int c4 = (i & 15) << 2;
        cp_async16(B + kk * TSTR + c4, hr + (k0 + kk) * NB + c4);
    }
    asm volatile("cp.async.commit_group;\n");
}

// ---------------- main persistent kernel ----------------
__global__ void __launch_bounds__(TPB, 1)
k_main(const float* __restrict__ inv_w, const float* __restrict__ inv_b,
       const float* __restrict__ lin_b, float* __restrict__ out) {
    extern __shared__ float sm[];
    float* shA  = sm;                 // 3 * TILEF
    float* shB  = sm + 3 * TILEF;     // 3 * TILEF
    float* shZ  = sm + 6 * TILEF;     // TILEF
    float* shC  = sm + 7 * TILEF;     // 1024 cell state (persistent)
    float* shIW = shC + 1024;         // 64
    float* shBB = shIW + 64;          // 64

    const int tid   = threadIdx.x;
    const int cta   = blockIdx.x;
    const int lane  = tid & 31;
    const int warp  = tid >> 5;
    const int rbase = (warp >> 1) * 32;
    const int cbase = (warp & 1) * 32;

    if (tid < 64) {
        int g  = tid >> 4;
        int kg = g * HID + cta * UPC + (tid & 15);
        shIW[tid] = inv_w[kg];
        shBB[tid] = inv_b[kg] + lin_b[kg];
    }
    for (int i = tid; i < 1024; i += TPB) shC[i] = 0.0f;
    __syncthreads();

    float acc[2][4][4];

    for (int t = 0; t < LT; ++t) {
        const float* hr = g_h[(t + 1) & 1];
        float*       hw = g_h[t & 1];

        #pragma unroll
        for (int rt = 0; rt < 2; ++rt)
            #pragma unroll
            for (int nt = 0; nt < 4; ++nt)
                #pragma unroll
                for (int j = 0; j < 4; ++j) acc[rt][nt][j] = 0.0f;

        load_chunk(0, tid, cta, hr, shA, shB);
        load_chunk(1, tid, cta, hr, shA, shB);

        #pragma unroll 1
        for (int ck = 0; ck < NCHUNK; ++ck) {
            if (ck < NCHUNK - 1) asm volatile("cp.async.wait_group 1;\n");
            else                 asm volatile("cp.async.wait_group 0;\n");
            __syncthreads();   // data visible + previous chunk's readers done
            if (ck < NCHUNK - 2) load_chunk(ck + 2, tid, cta, hr, shA, shB);

            const unsigned* A = (const unsigned*)(shA + (ck % 3) * TILEF);
            const unsigned* B = (const unsigned*)(shB + (ck % 3) * TILEF);
            #pragma unroll
            for (int ks = 0; ks < 8; ++ks) {
                unsigned a[2][4], b[4][2];
                int kcol = ks * 8 + (lane & 3);
                #pragma unroll
                for (int rt = 0; rt < 2; ++rt) {
                    int r0 = rbase + rt * 16 + (lane >> 2);
                    a[rt][0] = A[r0 * TSTR + kcol];
                    a[rt][1] = A[(r0 + 8) * TSTR + kcol];
                    a[rt][2] = A[r0 * TSTR + kcol + 4];
                    a[rt][3] = A[(r0 + 8) * TSTR + kcol + 4];
                }
                #pragma unroll
                for (int nt = 0; nt < 4; ++nt) {
                    int n0 = cbase + nt * 8 + (lane >> 2);
                    b[nt][0] = B[kcol * TSTR + n0];
                    b[nt][1] = B[(kcol + 4) * TSTR + n0];
                }
                #pragma unroll
                for (int rt = 0; rt < 2; ++rt)
                    #pragma unroll
                    for (int nt = 0; nt < 4; ++nt)
                        mma_tf32(acc[rt][nt], a[rt], b[nt]);
            }
        }

        // ---- epilogue: fragments -> shZ ----
        #pragma unroll
        for (int rt = 0; rt < 2; ++rt) {
            int r0 = rbase + rt * 16 + (lane >> 2);
            #pragma unroll
            for (int nt = 0; nt < 4; ++nt) {
                int n0 = cbase + nt * 8 + ((lane & 3) << 1);
                shZ[r0 * TSTR + n0]           = acc[rt][nt][0];
                shZ[r0 * TSTR + n0 + 1]       = acc[rt][nt][1];
                shZ[(r0 + 8) * TSTR + n0]     = acc[rt][nt][2];
                shZ[(r0 + 8) * TSTR + n0 + 1] = acc[rt][nt][3];
            }
        }
        __syncthreads();

        // ---- gates: 1024 (u, n) cells, 8 per thread ----
        for (int idx = tid; idx < 1024; idx += TPB) {
            int u = idx >> 6;
            int n = idx & 63;
            float s  = __ldg(&g_S[t * NB + n]);
            float zi = shZ[u * TSTR + n]        + shIW[u]      * s + shBB[u];
            float zf = shZ[(16 + u) * TSTR + n] + shIW[16 + u] * s + shBB[16 + u];
            float zg = shZ[(32 + u) * TSTR + n] + shIW[32 + u] * s + shBB[32 + u];
            float zo = shZ[(48 + u) * TSTR + n] + shIW[48 + u] * s + shBB[48 + u];
            float iv = sigmoid_f(zi);
            float fv = sigmoid_f(zf);
            float gv = tanh_f(zg);
            float ov = sigmoid_f(zo);
            float c  = fv * shC[idx] + iv * gv;
            shC[idx] = c;
            float h  = ov * tanh_f(c);
            int krow = cta * UPC + u;
            hw[krow * NB + n] = tf32_rna(h);
            if (t == LT - 1) out[krow * NB + n] = h;
        }

        grid_bar();
    }
}

// ---------------- launch ----------------
extern "C" void kernel_launch(void* const* d_in, const int* in_sizes, int n_in,
                              void* d_out, int out_size) {
    const float* X     = (const float*)d_in[0];
    const float* H0    = (const float*)d_in[1];
    const float* inv_w = (const float*)d_in[2];
    const float* inv_b = (const float*)d_in[3];
    const float* lin_W = (const float*)d_in[4];
    const float* lin_b = (const float*)d_in[5];
    float* out = (float*)d_out;

    cudaFuncSetAttribute(k_main, cudaFuncAttributeMaxDynamicSharedMemorySize, SMEM_BYTES);

    k_prep_w <<<16384, 256>>>(lin_W);
    k_prep_s <<<32768, 128>>>(X);
    k_prep_h0<<<512,   256>>>(H0);
    k_main   <<<NCTA, TPB, SMEM_BYTES>>>(inv_w, inv_b, lin_b, out);
}

// round 5
// speedup vs baseline: 1.2873x; 1.2873x over previous
#include <cuda_runtime.h>
#include <cstdint>
#include <cstddef>

#define NB     64
#define LT     512
#define DIN    1024
#define HID    2048
#define NCTA   128
#define UPC    16            // hidden units per CTA
#define TPB    256           // 8 warps: 2 K-split groups of 4
#define KC     64
#define NCHUNK_G 16          // chunks per group (K-half = 1024)
#define ASTR   68            // A tile row stride (floats): bank step 4 -> conflict-free
#define BSTR   72            // B tile row stride (floats): bank step 8 -> conflict-free
#define ZSTR   64
#define ATILE  (64 * ASTR)   // 4352 floats
#define BTILE  (64 * BSTR)   // 4608 floats
// smem: 4 A tiles (2 groups x 2 bufs) + 4 B tiles + Z + C + consts
#define SMEM_FLOATS (4 * ATILE + 4 * BTILE + 64 * ZSTR + 1024 + 128)
#define SMEM_BYTES  (SMEM_FLOATS * 4)

// ---------------- device globals (scratch) ----------------
__device__ __align__(16) float    g_Wt[4u * HID * HID];  // tf32-rounded weights
__device__ __align__(16) float    g_S[LT * NB];          // invariant sums S[t][n]
__device__ __align__(16) float    g_h[2][HID * NB];      // h double buffer, [k][n]
__device__ unsigned g_bar_count = 0;
__device__ unsigned g_bar_gen   = 0;

// ---------------- helpers ----------------
__device__ __forceinline__ float tf32_rna(float x) {
    unsigned u;
    asm("cvt.rna.tf32.f32 %0, %1;" : "=r"(u) : "f"(x));
    return __uint_as_float(u);
}

__device__ __forceinline__ void cp_async16(void* dst_smem, const void* src_gmem) {
    unsigned d = (unsigned)__cvta_generic_to_shared(dst_smem);
    asm volatile("cp.async.cg.shared.global [%0], [%1], 16;\n" :: "r"(d), "l"(src_gmem));
}

__device__ __forceinline__ void mma_tf32(float* c, const unsigned* a, const unsigned* b) {
    asm volatile(
        "mma.sync.aligned.m16n8k8.row.col.f32.tf32.tf32.f32 "
        "{%0,%1,%2,%3}, {%4,%5,%6,%7}, {%8,%9}, {%0,%1,%2,%3};\n"
        : "+f"(c[0]), "+f"(c[1]), "+f"(c[2]), "+f"(c[3])
        : "r"(a[0]), "r"(a[1]), "r"(a[2]), "r"(a[3]), "r"(b[0]), "r"(b[1]));
}

__device__ __forceinline__ float sigmoid_f(float x) { return 1.0f / (1.0f + __expf(-x)); }
__device__ __forceinline__ float tanh_f(float x)    { return 1.0f - 2.0f / (__expf(2.0f * x) + 1.0f); }

__device__ __forceinline__ void bar_group(int g) {
    asm volatile("bar.sync %0, 128;\n" :: "r"(g + 1) : "memory");
}

__device__ __forceinline__ void grid_bar() {
    __threadfence();
    __syncthreads();
    if (threadIdx.x == 0) {
        unsigned gen = *(volatile unsigned*)&g_bar_gen;
        __threadfence();
        if (atomicAdd(&g_bar_count, 1u) == NCTA - 1u) {
            g_bar_count = 0u;
            __threadfence();
            atomicAdd(&g_bar_gen, 1u);
        } else {
            while (*(volatile unsigned*)&g_bar_gen == gen) { __nanosleep(32); }
        }
    }
    __syncthreads();
}

// ---------------- prep kernels ----------------
__global__ void k_prep_w(const float* __restrict__ W) {
    size_t i = (size_t)blockIdx.x * 256 + threadIdx.x;   // 4,194,304 float4s
    float4 v = ((const float4*)W)[i];
    v.x = tf32_rna(v.x); v.y = tf32_rna(v.y);
    v.z = tf32_rna(v.z); v.w = tf32_rna(v.w);
    ((float4*)g_Wt)[i] = v;
}

__global__ void k_prep_s(const float* __restrict__ X) {
    __shared__ float red[4];
    int n = blockIdx.x >> 9;
    int t = blockIdx.x & 511;
    const float* p = X + ((size_t)n * LT + t) * DIN;
    float s = 0.0f;
    for (int d = threadIdx.x; d < DIN; d += 128) s += p[d];
    #pragma unroll
    for (int o = 16; o > 0; o >>= 1) s += __shfl_down_sync(0xffffffffu, s, o);
    if ((threadIdx.x & 31) == 0) red[threadIdx.x >> 5] = s;
    __syncthreads();
    if (threadIdx.x == 0) g_S[t * NB + n] = red[0] + red[1] + red[2] + red[3];
}

__global__ void k_prep_h0(const float* __restrict__ H0) {
    int i = blockIdx.x * 256 + threadIdx.x;  // 131072 elements; H0 is [n][k]
    int n = i >> 11;
    int k = i & 2047;
    g_h[1][k * NB + n] = tf32_rna(H0[i]);    // step 0 reads buffer 1
}

// ---------------- chunk loader (one K-group, one chunk) ----------------
// 128 threads of the group load A(64x64) + B(64x64) for chunk ck of group grp.
__device__ __forceinline__ void load_chunk(int grp, int ck, int gt, int cta,
                                           const float* __restrict__ hr,
                                           float* shA, float* shB) {
    int buf = ck & 1;
    int k0  = grp * 1024 + ck * KC;
    float* A = shA + (grp * 2 + buf) * ATILE;
    float* B = shB + (grp * 2 + buf) * BTILE;
    #pragma unroll
    for (int i = gt; i < 1024; i += 128) {      // 64 rows x 16 float4
        int r  = i >> 4;
        int c4 = (i & 15) << 2;
        const float* src =
            g_Wt + ((size_t)((r >> 4) * HID + cta * UPC + (r & 15))) * HID + k0 + c4;
        cp_async16(A + r * ASTR + c4, src);
    }
    #pragma unroll
    for (int i = gt; i < 1024; i += 128) {      // 64 k-rows x 16 float4
        int kk = i >> 4;
        int c4 = (i & 15) << 2;
        cp_async16(B + kk * BSTR + c4, hr + (size_t)(k0 + kk) * NB + c4);
    }
    asm volatile("cp.async.commit_group;\n");
}

// ---------------- main persistent kernel ----------------
__global__ void __launch_bounds__(TPB, 1)
k_main(const float* __restrict__ inv_w, const float* __restrict__ inv_b,
       const float* __restrict__ lin_b, float* __restrict__ out) {
    extern __shared__ float sm[];
    float* shA  = sm;                          // 4 * ATILE
    float* shB  = sm + 4 * ATILE;              // 4 * BTILE
    float* shZ  = sm + 4 * ATILE + 4 * BTILE;  // 64 * ZSTR
    float* shC  = shZ + 64 * ZSTR;             // 1024 cell state
    float* shIW = shC + 1024;                  // 64
    float* shBB = shIW + 64;                   // 64

    const int tid   = threadIdx.x;
    const int cta   = blockIdx.x;
    const int lane  = tid & 31;
    const int warp  = tid >> 5;
    const int grp   = warp >> 2;        // K-split group: 0 or 1
    const int w     = warp & 3;         // warp within group
    const int gt    = tid & 127;        // thread id within group
    const int rbase = (w >> 1) * 32;
    const int cbase = (w & 1) * 32;

    if (tid < 64) {
        int g  = tid >> 4;
        int kg = g * HID + cta * UPC + (tid & 15);
        shIW[tid] = inv_w[kg];
        shBB[tid] = inv_b[kg] + lin_b[kg];
    }
    for (int i = tid; i < 1024; i += TPB) shC[i] = 0.0f;
    __syncthreads();

    float acc[2][4][4];

    for (int t = 0; t < LT; ++t) {
        const float* hr = g_h[(t + 1) & 1];
        float*       hw = g_h[t & 1];

        #pragma unroll
        for (int rt = 0; rt < 2; ++rt)
            #pragma unroll
            for (int nt = 0; nt < 4; ++nt)
                #pragma unroll
                for (int j = 0; j < 4; ++j) acc[rt][nt][j] = 0.0f;

        load_chunk(grp, 0, gt, cta, hr, shA, shB);

        #pragma unroll 1
        for (int ck = 0; ck < NCHUNK_G; ++ck) {
            asm volatile("cp.async.wait_group 0;\n");
            bar_group(grp);   // data visible to group + prev chunk's readers done
            if (ck < NCHUNK_G - 1) load_chunk(grp, ck + 1, gt, cta, hr, shA, shB);

            const unsigned* A = (const unsigned*)(shA + (grp * 2 + (ck & 1)) * ATILE);
            const unsigned* B = (const unsigned*)(shB + (grp * 2 + (ck & 1)) * BTILE);
            #pragma unroll
            for (int ks = 0; ks < 8; ++ks) {
                unsigned a[2][4], b[4][2];
                int kcol = ks * 8 + (lane & 3);
                #pragma unroll
                for (int rt = 0; rt < 2; ++rt) {
                    int r0 = rbase + rt * 16 + (lane >> 2);
                    a[rt][0] = A[r0 * ASTR + kcol];
                    a[rt][1] = A[(r0 + 8) * ASTR + kcol];
                    a[rt][2] = A[r0 * ASTR + kcol + 4];
                    a[rt][3] = A[(r0 + 8) * ASTR + kcol + 4];
                }
                #pragma unroll
                for (int nt = 0; nt < 4; ++nt) {
                    int n0 = cbase + nt * 8 + (lane >> 2);
                    b[nt][0] = B[kcol * BSTR + n0];
                    b[nt][1] = B[(kcol + 4) * BSTR + n0];
                }
                #pragma unroll
                for (int rt = 0; rt < 2; ++rt)
                    #pragma unroll
                    for (int nt = 0; nt < 4; ++nt)
                        mma_tf32(acc[rt][nt], a[rt], b[nt]);
            }
        }

        // ---- partial-Z reduction: group 0 writes, group 1 adds ----
        __syncthreads();
        if (grp == 0) {
            #pragma unroll
            for (int rt = 0; rt < 2; ++rt) {
                int r0 = rbase + rt * 16 + (lane >> 2);
                #pragma unroll
                for (int nt = 0; nt < 4; ++nt) {
                    int n0 = cbase + nt * 8 + ((lane & 3) << 1);
                    shZ[r0 * ZSTR + n0]           = acc[rt][nt][0];
                    shZ[r0 * ZSTR + n0 + 1]       = acc[rt][nt][1];
                    shZ[(r0 + 8) * ZSTR + n0]     = acc[rt][nt][2];
                    shZ[(r0 + 8) * ZSTR + n0 + 1] = acc[rt][nt][3];
                }
            }
        }
        __syncthreads();
        if (grp == 1) {
            #pragma unroll
            for (int rt = 0; rt < 2; ++rt) {
                int r0 = rbase + rt * 16 + (lane >> 2);
                #pragma unroll
                for (int nt = 0; nt < 4; ++nt) {
                    int n0 = cbase + nt * 8 + ((lane & 3) << 1);
                    shZ[r0 * ZSTR + n0]           += acc[rt][nt][0];
                    shZ[r0 * ZSTR + n0 + 1]       += acc[rt][nt][1];
                    shZ[(r0 + 8) * ZSTR + n0]     += acc[rt][nt][2];
                    shZ[(r0 + 8) * ZSTR + n0 + 1] += acc[rt][nt][3];
                }
            }
        }
        __syncthreads();

        // ---- gates: 1024 (u, n) cells, 4 per thread ----
        for (int idx = tid; idx < 1024; idx += TPB) {
            int u = idx >> 6;
            int n = idx & 63;
            float s  = __ldg(&g_S[t * NB + n]);
            float zi = shZ[u * ZSTR + n]        + shIW[u]      * s + shBB[u];
            float zf = shZ[(16 + u) * ZSTR + n] + shIW[16 + u] * s + shBB[16 + u];
            float zg = shZ[(32 + u) * ZSTR + n] + shIW[32 + u] * s + shBB[32 + u];
            float zo = shZ[(48 + u) * ZSTR + n] + shIW[48 + u] * s + shBB[48 + u];
            float iv = sigmoid_f(zi);
            float fv = sigmoid_f(zf);
            float gv = tanh_f(zg);
            float ov = sigmoid_f(zo);
            float c  = fv * shC[idx] + iv * gv;
            shC[idx] = c;
            float h  = ov * tanh_f(c);
            int krow = cta * UPC + u;
            hw[(size_t)krow * NB + n] = tf32_rna(h);
            if (t == LT - 1) out[(size_t)krow * NB + n] = h;
        }

        grid_bar();
    }
}

// ---------------- launch ----------------
extern "C" void kernel_launch(void* const* d_in, const int* in_sizes, int n_in,
                              void* d_out, int out_size) {
    const float* X     = (const float*)d_in[0];
    const float* H0    = (const float*)d_in[1];
    const float* inv_w = (const float*)d_in[2];
    const float* inv_b = (const float*)d_in[3];
    const float* lin_W = (const float*)d_in[4];
    const float* lin_b = (const float*)d_in[5];
    float* out = (float*)d_out;

    cudaFuncSetAttribute(k_main, cudaFuncAttributeMaxDynamicSharedMemorySize, SMEM_BYTES);

    k_prep_w <<<16384, 256>>>(lin_W);
    k_prep_s <<<32768, 128>>>(X);
    k_prep_h0<<<512,   256>>>(H0);
    k_main   <<<NCTA, TPB, SMEM_BYTES>>>(inv_w, inv_b, lin_b, out);
}

// round 11
// speedup vs baseline: 1.4693x; 1.1414x over previous
#include <cuda_runtime.h>
#include <cstdint>
#include <cstddef>

#define NB     64
#define LT     512
#define DIN    1024
#define HID    2048
#define NCTA   128
#define UPC    16            // hidden units per CTA
#define TPB    512           // 16 warps: 4 K-split groups of 4 warps
#define KC     32            // K per chunk
#define NCHUNK_G 16          // chunks per group (K-quarter = 512 = 16 * 32)
#define ASTR   36            // A tile row stride (floats): bank step 4 -> conflict-free
#define BSTR   72            // B tile row stride (floats): bank step 8 -> conflict-free
#define ZSTR   65
#define ATILE  (64 * ASTR)   // 2304 floats (64 rows x 32 k)
#define BTILE  (32 * BSTR)   // 2304 floats (32 k x 64 n)

// ---- SMEM float offsets ----
#define AOFF   0                          // 8 A tiles (4 groups x 2 bufs)
#define BOFF   (8 * ATILE)                // 8 B tiles
#define Z0OFF  (8 * (ATILE + BTILE))      // 36864
#define Z1OFF  (Z0OFF + 64 * ZSTR)        // +4160
#define COFF   (Z1OFF + 64 * ZSTR)        // cell state, 1024
#define IWOFF  (COFF + 1024)
#define BBOFF  (IWOFF + 64)
#define SMEM_FLOATS (BBOFF + 64)
#define SMEM_BYTES  (SMEM_FLOATS * 4)     // ~185 KB

// ---------------- device globals (scratch) ----------------
__device__ __align__(16) float    g_Wt[4u * HID * HID];  // tf32-rounded weights
__device__ __align__(16) float    g_S[LT * NB];          // invariant sums S[t][n]
__device__ __align__(16) float    g_h[2][HID * NB];      // h double buffer, [k][n]
__device__ unsigned g_bar_count = 0;
__device__ unsigned g_bar_gen   = 0;

// ---------------- helpers ----------------
__device__ __forceinline__ float tf32_rna(float x) {
    unsigned u;
    asm("cvt.rna.tf32.f32 %0, %1;" : "=r"(u) : "f"(x));
    return __uint_as_float(u);
}

__device__ __forceinline__ void cp_async16(void* dst_smem, const void* src_gmem) {
    unsigned d = (unsigned)__cvta_generic_to_shared(dst_smem);
    asm volatile("cp.async.cg.shared.global [%0], [%1], 16;\n" :: "r"(d), "l"(src_gmem));
}

__device__ __forceinline__ void mma_tf32(float* c, const unsigned* a, const unsigned* b) {
    asm volatile(
        "mma.sync.aligned.m16n8k8.row.col.f32.tf32.tf32.f32 "
        "{%0,%1,%2,%3}, {%4,%5,%6,%7}, {%8,%9}, {%0,%1,%2,%3};\n"
        : "+f"(c[0]), "+f"(c[1]), "+f"(c[2]), "+f"(c[3])
        : "r"(a[0]), "r"(a[1]), "r"(a[2]), "r"(a[3]), "r"(b[0]), "r"(b[1]));
}

__device__ __forceinline__ float sigmoid_f(float x) { return 1.0f / (1.0f + __expf(-x)); }
__device__ __forceinline__ float tanh_f(float x)    { return 1.0f - 2.0f / (__expf(2.0f * x) + 1.0f); }

__device__ __forceinline__ void bar_group(int g) {
    asm volatile("bar.sync %0, 128;\n" :: "r"(g + 1) : "memory");
}

__device__ __forceinline__ void grid_bar() {
    __threadfence();
    __syncthreads();
    if (threadIdx.x == 0) {
        unsigned gen = *(volatile unsigned*)&g_bar_gen;
        __threadfence();
        if (atomicAdd(&g_bar_count, 1u) == NCTA - 1u) {
            g_bar_count = 0u;
            __threadfence();
            atomicAdd(&g_bar_gen, 1u);
        } else {
            while (*(volatile unsigned*)&g_bar_gen == gen) { __nanosleep(32); }
        }
    }
    __syncthreads();
}

// ---------------- prep kernels ----------------
__global__ void k_prep_w(const float* __restrict__ W) {
    size_t i = (size_t)blockIdx.x * 256 + threadIdx.x;   // 4,194,304 float4s
    float4 v = ((const float4*)W)[i];
    v.x = tf32_rna(v.x); v.y = tf32_rna(v.y);
    v.z = tf32_rna(v.z); v.w = tf32_rna(v.w);
    ((float4*)g_Wt)[i] = v;
}

__global__ void k_prep_s(const float* __restrict__ X) {
    __shared__ float red[4];
    int n = blockIdx.x >> 9;
    int t = blockIdx.x & 511;
    const float* p = X + ((size_t)n * LT + t) * DIN;
    float s = 0.0f;
    for (int d = threadIdx.x; d < DIN; d += 128) s += p[d];
    #pragma unroll
    for (int o = 16; o > 0; o >>= 1) s += __shfl_down_sync(0xffffffffu, s, o);
    if ((threadIdx.x & 31) == 0) red[threadIdx.x >> 5] = s;
    __syncthreads();
    if (threadIdx.x == 0) g_S[t * NB + n] = red[0] + red[1] + red[2] + red[3];
}

__global__ void k_prep_h0(const float* __restrict__ H0) {
    int i = blockIdx.x * 256 + threadIdx.x;  // 131072; H0 is [n][k]
    int n = i >> 11;
    int k = i & 2047;
    g_h[1][k * NB + n] = tf32_rna(H0[i]);    // step 0 reads buffer 1
}

// ---------------- chunk loader (one group, one chunk) ----------------
// 128 threads of group grp load A(64x32) + B(32x64) for chunk ck.
__device__ __forceinline__ void load_chunk(int grp, int ck, int gt, int cta,
                                           const float* __restrict__ hr,
                                           float* __restrict__ sm) {
    int buf = ck & 1;
    int k0  = grp * 512 + ck * KC;
    float* A = sm + AOFF + (grp * 2 + buf) * ATILE;
    float* B = sm + BOFF + (grp * 2 + buf) * BTILE;
    #pragma unroll
    for (int j = 0; j < 4; ++j) {            // A: 512 16B units (64 rows x 8)
        int i = gt + j * 128;
        int r = i >> 3, c4 = (i & 7) << 2;
        const float* src =
            g_Wt + ((size_t)((r >> 4) * HID + cta * UPC + (r & 15))) * HID + k0 + c4;
        cp_async16(A + r * ASTR + c4, src);
    }
    #pragma unroll
    for (int j = 0; j < 4; ++j) {            // B: 512 16B units (32 k-rows x 16)
        int i = gt + j * 128;
        int kk = i >> 4, c4 = (i & 15) << 2;
        cp_async16(B + kk * BSTR + c4, hr + (size_t)(k0 + kk) * NB + c4);
    }
    asm volatile("cp.async.commit_group;\n");
}

// ---------------- main persistent kernel ----------------
__global__ void __launch_bounds__(TPB, 1)
k_main(const float* __restrict__ inv_w, const float* __restrict__ inv_b,
       const float* __restrict__ lin_b, float* __restrict__ out) {
    extern __shared__ float sm[];

    const int tid   = threadIdx.x;
    const int cta   = blockIdx.x;
    const int lane  = tid & 31;
    const int warp  = tid >> 5;
    const int grp   = warp >> 2;        // K-split group: 0..3
    const int w     = warp & 3;         // warp within group
    const int gt    = tid & 127;        // thread id within group
    const int rbase = (w >> 1) * 32;
    const int cbase = (w & 1) * 32;

    if (tid < 64) {
        int g  = tid >> 4;
        int kg = g * HID + cta * UPC + (tid & 15);
        sm[IWOFF + tid] = inv_w[kg];
        sm[BBOFF + tid] = inv_b[kg] + lin_b[kg];
    }
    for (int i = tid; i < 1024; i += TPB) sm[COFF + i] = 0.0f;
    __syncthreads();

    float acc[2][4][4];

    for (int t = 0; t < LT; ++t) {
        const float* hr = g_h[(t + 1) & 1];
        float*       hw = g_h[t & 1];

        #pragma unroll
        for (int rt = 0; rt < 2; ++rt)
            #pragma unroll
            for (int nt = 0; nt < 4; ++nt)
                #pragma unroll
                for (int j = 0; j < 4; ++j) acc[rt][nt][j] = 0.0f;

        load_chunk(grp, 0, gt, cta, hr, sm);

        #pragma unroll 1
        for (int ck = 0; ck < NCHUNK_G; ++ck) {
            asm volatile("cp.async.wait_group 0;\n" ::: "memory");
            bar_group(grp);   // data visible to group + prev chunk's readers done
            if (ck < NCHUNK_G - 1) load_chunk(grp, ck + 1, gt, cta, hr, sm);

            const unsigned* A = (const unsigned*)(sm + AOFF + (grp * 2 + (ck & 1)) * ATILE);
            const unsigned* B = (const unsigned*)(sm + BOFF + (grp * 2 + (ck & 1)) * BTILE);
            #pragma unroll
            for (int ks = 0; ks < 4; ++ks) {
                unsigned a[2][4], b[4][2];
                int kcol = ks * 8 + (lane & 3);
                #pragma unroll
                for (int rt = 0; rt < 2; ++rt) {
                    int r0 = rbase + rt * 16 + (lane >> 2);
                    a[rt][0] = A[r0 * ASTR + kcol];
                    a[rt][1] = A[(r0 + 8) * ASTR + kcol];
                    a[rt][2] = A[r0 * ASTR + kcol + 4];
                    a[rt][3] = A[(r0 + 8) * ASTR + kcol + 4];
                }
                #pragma unroll
                for (int nt = 0; nt < 4; ++nt) {
                    int n0 = cbase + nt * 8 + (lane >> 2);
                    b[nt][0] = B[kcol * BSTR + n0];
                    b[nt][1] = B[(kcol + 4) * BSTR + n0];
                }
                #pragma unroll
                for (int rt = 0; rt < 2; ++rt)
                    #pragma unroll
                    for (int nt = 0; nt < 4; ++nt)
                        mma_tf32(acc[rt][nt], a[rt], b[nt]);
            }
        }

        // ---- partial-Z reduction: grp0/grp1 write Z0/Z1; grp2/grp3 add ----
        __syncthreads();
        {
            float* Z = sm + ((grp & 1) ? Z1OFF : Z0OFF);
            if (grp < 2) {
                #pragma unroll
                for (int rt = 0; rt < 2; ++rt) {
                    int r0 = rbase + rt * 16 + (lane >> 2);
                    #pragma unroll
                    for (int nt = 0; nt < 4; ++nt) {
                        int n0 = cbase + nt * 8 + ((lane & 3) << 1);
                        Z[r0 * ZSTR + n0]           = acc[rt][nt][0];
                        Z[r0 * ZSTR + n0 + 1]       = acc[rt][nt][1];
                        Z[(r0 + 8) * ZSTR + n0]     = acc[rt][nt][2];
                        Z[(r0 + 8) * ZSTR + n0 + 1] = acc[rt][nt][3];
                    }
                }
            }
            __syncthreads();
            if (grp >= 2) {
                #pragma unroll
                for (int rt = 0; rt < 2; ++rt) {
                    int r0 = rbase + rt * 16 + (lane >> 2);
                    #pragma unroll
                    for (int nt = 0; nt < 4; ++nt) {
                        int n0 = cbase + nt * 8 + ((lane & 3) << 1);
                        Z[r0 * ZSTR + n0]           += acc[rt][nt][0];
                        Z[r0 * ZSTR + n0 + 1]       += acc[rt][nt][1];
                        Z[(r0 + 8) * ZSTR + n0]     += acc[rt][nt][2];
                        Z[(r0 + 8) * ZSTR + n0 + 1] += acc[rt][nt][3];
                    }
                }
            }
        }
        __syncthreads();

        // ---- gates: 1024 (u, n) cells, 2 per thread ----
        for (int idx = tid; idx < 1024; idx += TPB) {
            int u = idx >> 6;
            int n = idx & 63;
            float s  = __ldg(&g_S[t * NB + n]);
            float zi = sm[Z0OFF + u * ZSTR + n]        + sm[Z1OFF + u * ZSTR + n]
                     + sm[IWOFF + u] * s + sm[BBOFF + u];
            float zf = sm[Z0OFF + (16 + u) * ZSTR + n] + sm[Z1OFF + (16 + u) * ZSTR + n]
                     + sm[IWOFF + 16 + u] * s + sm[BBOFF + 16 + u];
            float zg = sm[Z0OFF + (32 + u) * ZSTR + n] + sm[Z1OFF + (32 + u) * ZSTR + n]
                     + sm[IWOFF + 32 + u] * s + sm[BBOFF + 32 + u];
            float zo = sm[Z0OFF + (48 + u) * ZSTR + n] + sm[Z1OFF + (48 + u) * ZSTR + n]
                     + sm[IWOFF + 48 + u] * s + sm[BBOFF + 48 + u];
            float iv = sigmoid_f(zi);
            float fv = sigmoid_f(zf);
            float gv = tanh_f(zg);
            float ov = sigmoid_f(zo);
            float c  = fv * sm[COFF + idx] + iv * gv;
            sm[COFF + idx] = c;
            float h  = ov * tanh_f(c);
            int krow = cta * UPC + u;
            hw[(size_t)krow * NB + n] = tf32_rna(h);
            if (t == LT - 1) out[(size_t)krow * NB + n] = h;
        }

        grid_bar();
    }
}

// ---------------- launch ----------------
extern "C" void kernel_launch(void* const* d_in, const int* in_sizes, int n_in,
                              void* d_out, int out_size) {
    const float* X     = (const float*)d_in[0];
    const float* H0    = (const float*)d_in[1];
    const float* inv_w = (const float*)d_in[2];
    const float* inv_b = (const float*)d_in[3];
    const float* lin_W = (const float*)d_in[4];
    const float* lin_b = (const float*)d_in[5];
    float* out = (float*)d_out;

    cudaFuncSetAttribute(k_main, cudaFuncAttributeMaxDynamicSharedMemorySize, SMEM_BYTES);

    k_prep_w <<<16384, 256>>>(lin_W);
    k_prep_s <<<32768, 128>>>(X);
    k_prep_h0<<<512,   256>>>(H0);
    k_main   <<<NCTA, TPB, SMEM_BYTES>>>(inv_w, inv_b, lin_b, out);
}